// round 11
// baseline (speedup 1.0000x reference)
#include <cuda_runtime.h>
#include <cuda_bf16.h>
#include <cuda_fp16.h>
#include <math.h>
#include <stdint.h>

#define T_TOK 2048
#define DIM   1024
#define NEXP  8
#define HID   2048

#define BM 128
#define BN 128
#define BK 32              // K elements per chunk
#define ROWB 80            // padded row stride bytes (40 halves) -> conflict-free ldmatrix
#define PB (128 * ROWB)    // plane bytes = 10240

#define TD (T_TOK * DIM)

// ---------------- scratch (device globals; no allocation allowed) ----------
__device__ int   g_cnt[NEXP];
__device__ int   g_tok[NEXP * T_TOK];    // t | (slot << 12)
__device__ float g_wgt[NEXP * T_TOK];
__device__ __align__(256) __half g_x_hi[T_TOK * DIM];
__device__ __align__(256) __half g_x_lo[T_TOK * DIM];
__device__ __align__(256) __half g_wu[NEXP * HID * DIM];
__device__ __align__(256) __half g_wd[NEXP * DIM * HID];
__device__ __align__(256) __half g_h[(size_t)NEXP * T_TOK * HID];
__device__ __align__(256) float  g_part[2 * TD];   // down partials (slot 0 / 1)

// ---------------- helpers ---------------------------------------------------
__device__ __forceinline__ uint32_t smem_u32(const void* p) {
    return (uint32_t)__cvta_generic_to_shared(p);
}
__device__ __forceinline__ void cpa16(uint32_t dst, const void* src) {
    asm volatile("cp.async.cg.shared.global [%0], [%1], 16;\n"
                 :: "r"(dst), "l"(src) : "memory");
}
__device__ __forceinline__ void ldmx4(uint32_t& r0, uint32_t& r1, uint32_t& r2,
                                      uint32_t& r3, uint32_t addr) {
    asm volatile("ldmatrix.sync.aligned.m8n8.x4.shared.b16 {%0,%1,%2,%3}, [%4];\n"
                 : "=r"(r0), "=r"(r1), "=r"(r2), "=r"(r3) : "r"(addr));
}
__device__ __forceinline__ void mma_fp16(float* d, const uint32_t* a, const uint32_t* b) {
    asm volatile("mma.sync.aligned.m16n8k16.row.col.f32.f16.f16.f32 "
                 "{%0,%1,%2,%3}, {%4,%5,%6,%7}, {%8,%9}, {%0,%1,%2,%3};\n"
                 : "+f"(d[0]), "+f"(d[1]), "+f"(d[2]), "+f"(d[3])
                 : "r"(a[0]), "r"(a[1]), "r"(a[2]), "r"(a[3]), "r"(b[0]), "r"(b[1]));
}

// ---------------- router ----------------------------------------------------
__global__ void init_counts_kernel() {
    if (threadIdx.x < NEXP) g_cnt[threadIdx.x] = 0;
}

__global__ void router_kernel(const float* __restrict__ x,
                              const float* __restrict__ gate_w,
                              const float* __restrict__ bias) {
    int warp = threadIdx.x >> 5;
    int lane = threadIdx.x & 31;
    int t = blockIdx.x * 4 + warp;
    if (t >= T_TOK) return;

    float s[NEXP];
#pragma unroll
    for (int e = 0; e < NEXP; e++) s[e] = 0.f;
    const float* xr = x + (size_t)t * DIM;
    for (int d = lane; d < DIM; d += 32) {
        float xv = xr[d];
#pragma unroll
        for (int e = 0; e < NEXP; e++) s[e] += xv * gate_w[e * DIM + d];
    }
#pragma unroll
    for (int e = 0; e < NEXP; e++)
#pragma unroll
        for (int o = 16; o > 0; o >>= 1)
            s[e] += __shfl_xor_sync(0xffffffffu, s[e], o);

    if (lane == 0) {
        float sig[NEXP], b[NEXP];
#pragma unroll
        for (int e = 0; e < NEXP; e++) {
            sig[e] = 1.f / (1.f + expf(-s[e]));
            b[e] = sig[e] + bias[e];
        }
        int e0 = 0;
        for (int e = 1; e < NEXP; e++) if (b[e] > b[e0]) e0 = e;
        int e1 = -1;
        for (int e = 0; e < NEXP; e++) {
            if (e == e0) continue;
            if (e1 < 0 || b[e] > b[e1]) e1 = e;
        }
        int p0 = atomicAdd(&g_cnt[e0], 1);
        g_tok[e0 * T_TOK + p0] = t;                 // slot 0
        g_wgt[e0 * T_TOK + p0] = sig[e0];
        int p1 = atomicAdd(&g_cnt[e1], 1);
        g_tok[e1 * T_TOK + p1] = t | (1 << 12);     // slot 1
        g_wgt[e1 * T_TOK + p1] = sig[e1];
    }
}

// ---------------- fused prepass ----------------------------------------------
// region 0: x -> fp16 hi/lo split; region 1: w_up -> fp16; region 2: w_down -> fp16
__global__ void prepass_kernel(const float* __restrict__ x,
                               const float* __restrict__ w_up,
                               const float* __restrict__ w_down) {
    constexpr int NX  = T_TOK * DIM;
    constexpr int NWU = NEXP * HID * DIM;
    constexpr int NWD = NEXP * DIM * HID;
    int i4 = (blockIdx.x * blockDim.x + threadIdx.x) * 4;
    if (i4 < NX) {
        float4 v = *(const float4*)(x + i4);
        float f[4] = {v.x, v.y, v.z, v.w};
        __half h[4], l[4];
#pragma unroll
        for (int j = 0; j < 4; j++) {
            h[j] = __float2half_rn(f[j]);
            l[j] = __float2half_rn(f[j] - __half2float(h[j]));
        }
        *(uint2*)(g_x_hi + i4) = *(uint2*)h;
        *(uint2*)(g_x_lo + i4) = *(uint2*)l;
    } else if (i4 < NX + NWU + NWD) {
        const float* src; __half* dst; int off;
        if (i4 < NX + NWU) { off = i4 - NX;       src = w_up;   dst = g_wu; }
        else               { off = i4 - NX - NWU; src = w_down; dst = g_wd; }
        float4 v = *(const float4*)(src + off);
        __half2 a = __floats2half2_rn(v.x, v.y);
        __half2 b = __floats2half2_rn(v.z, v.w);
        *(uint2*)(dst + off) = make_uint2(*(uint32_t*)&a, *(uint32_t*)&b);
    }
}

// ---------------- grouped GEMM ----------------------------------------------
// MODE 0 (up):   2-term fp16: z = Ahi@B + Alo@B; A = gather(x hi/lo), B = wu
//                epilogue h = (s*relu(z))^2 -> fp16   [3 planes, 3 stages]
// MODE 1 (down): 1-term fp16: A = h, B = wd; epilogue STG to g_part[slot]
//                [2 planes, 4 stages]
template <int MODE>
__global__ __launch_bounds__(256, 2)
void moe_gemm_kernel() {
    constexpr int KT     = (MODE == 0) ? DIM : HID;
    constexpr int NC     = KT / BK;
    constexpr int STAGES = (MODE == 0) ? 3 : 4;
    constexpr int PLANES = (MODE == 0) ? 3 : 2;   // up: Ahi,Alo,B; down: A,B

    const int e   = blockIdx.z;
    const int cnt = g_cnt[e];
    const int i0  = blockIdx.y * BM;
    if (i0 >= cnt) return;
    const int j0  = blockIdx.x * BN;

    extern __shared__ __align__(1024) char smem_dyn[];
    __shared__ int   row_tok_s[BM];
    __shared__ float row_w_s[BM];
    const uint32_t sbase = smem_u32(smem_dyn);

    const int tid = threadIdx.x, warp = tid >> 5, lane = tid & 31;
    const int wm = warp & 3, wn = warp >> 2;
    const int rm = wm * 32, cn = wn * 64;

    for (int i = tid; i < BM; i += 256) {
        int gi = i0 + i; int tk = 0; float w = 0.f;
        if (gi < cnt) { tk = g_tok[e * T_TOK + gi]; w = g_wgt[e * T_TOK + gi]; }
        row_tok_s[i] = tk; row_w_s[i] = w;
    }
    __syncthreads();

    float acc[2][8][4];
#pragma unroll
    for (int a = 0; a < 2; a++)
#pragma unroll
        for (int b = 0; b < 8; b++)
#pragma unroll
            for (int c = 0; c < 4; c++) acc[a][b][c] = 0.f;

    auto load_chunk = [&](int c) {
        const int k0 = c * BK;
        const uint32_t st = sbase + (uint32_t)(c % STAGES) * PLANES * PB;
#pragma unroll
        for (int p = 0; p < PLANES; p++) {
#pragma unroll
            for (int q = 0; q < 2; q++) {
                int id  = tid + q * 256;          // 0..511
                int r   = id >> 2;                // row 0..127
                int c16 = id & 3;                 // 16B chunk in 64B row payload
                const void* src;
                if (MODE == 0) {
                    if (p < 2) {
                        const __half* base = (p == 0) ? g_x_hi : g_x_lo;
                        src = base + (size_t)(row_tok_s[r] & 0xFFF) * DIM + k0 + c16 * 8;
                    } else {
                        src = g_wu + ((size_t)e * HID + j0 + r) * DIM + k0 + c16 * 8;
                    }
                } else {
                    if (p == 0)
                        src = g_h + ((size_t)e * T_TOK + i0 + r) * HID + k0 + c16 * 8;
                    else
                        src = g_wd + ((size_t)e * DIM + j0 + r) * HID + k0 + c16 * 8;
                }
                cpa16(st + (uint32_t)p * PB + (uint32_t)(r * ROWB + c16 * 16), src);
            }
        }
        asm volatile("cp.async.commit_group;\n" ::: "memory");
    };

    // prologue: fill STAGES-1 stages
#pragma unroll
    for (int c = 0; c < STAGES - 1; c++) load_chunk(c);

    for (int c = 0; c < NC; c++) {
        // Steady state: STAGES-1 groups pending (chunks c..c+STAGES-2);
        // wait_group(STAGES-2) retires exactly chunk c.
        // Tail (no more commits): pending can be <= STAGES-2 WITHOUT chunk c
        // being complete, so we must drain fully (wait_group 0).
        if (c + STAGES - 1 < NC) {
            asm volatile("cp.async.wait_group %0;\n" :: "n"(STAGES - 2) : "memory");
        } else {
            asm volatile("cp.async.wait_group 0;\n" ::: "memory");
        }
        __syncthreads();   // chunk c visible to all; all warps done with chunk c-1
        if (c + STAGES - 1 < NC) load_chunk(c + STAGES - 1);

        const uint32_t st = sbase + (uint32_t)(c % STAGES) * PLANES * PB;
#pragma unroll
        for (int kk = 0; kk < BK; kk += 16) {
            if (MODE == 0) {
                uint32_t af[2][2][4];
#pragma unroll
                for (int part = 0; part < 2; part++)
#pragma unroll
                    for (int mi = 0; mi < 2; mi++) {
                        uint32_t addr = st + (uint32_t)part * PB +
                            (uint32_t)((rm + mi * 16 + (lane & 15)) * ROWB +
                                       (kk + (lane >> 4) * 8) * 2);
                        ldmx4(af[part][mi][0], af[part][mi][1],
                              af[part][mi][2], af[part][mi][3], addr);
                    }
                uint32_t bf[8][2];
#pragma unroll
                for (int nb = 0; nb < 4; nb++) {
                    int nrow = cn + nb * 16 + (lane & 7) + (((lane >> 4) & 1) << 3);
                    int kcol = kk + ((lane & 8) ? 8 : 0);
                    uint32_t addr = st + 2u * PB + (uint32_t)(nrow * ROWB + kcol * 2);
                    uint32_t r0, r1, r2, r3;
                    ldmx4(r0, r1, r2, r3, addr);
                    bf[nb * 2][0] = r0;      bf[nb * 2][1] = r1;
                    bf[nb * 2 + 1][0] = r2;  bf[nb * 2 + 1][1] = r3;
                }
#pragma unroll
                for (int mi = 0; mi < 2; mi++)
#pragma unroll
                    for (int ni = 0; ni < 8; ni++) {
                        mma_fp16(acc[mi][ni], af[0][mi], bf[ni]);
                        mma_fp16(acc[mi][ni], af[1][mi], bf[ni]);
                    }
            } else {
                uint32_t af[2][4];
#pragma unroll
                for (int mi = 0; mi < 2; mi++) {
                    uint32_t addr = st +
                        (uint32_t)((rm + mi * 16 + (lane & 15)) * ROWB +
                                   (kk + (lane >> 4) * 8) * 2);
                    ldmx4(af[mi][0], af[mi][1], af[mi][2], af[mi][3], addr);
                }
                uint32_t bf[8][2];
#pragma unroll
                for (int nb = 0; nb < 4; nb++) {
                    int nrow = cn + nb * 16 + (lane & 7) + (((lane >> 4) & 1) << 3);
                    int kcol = kk + ((lane & 8) ? 8 : 0);
                    uint32_t addr = st + PB + (uint32_t)(nrow * ROWB + kcol * 2);
                    uint32_t r0, r1, r2, r3;
                    ldmx4(r0, r1, r2, r3, addr);
                    bf[nb * 2][0] = r0;      bf[nb * 2][1] = r1;
                    bf[nb * 2 + 1][0] = r2;  bf[nb * 2 + 1][1] = r3;
                }
#pragma unroll
                for (int mi = 0; mi < 2; mi++)
#pragma unroll
                    for (int ni = 0; ni < 8; ni++)
                        mma_fp16(acc[mi][ni], af[mi], bf[ni]);
            }
        }
    }

    // ---------------- epilogue ----------------
    const int tg = lane >> 2;          // 0..7
    const int tc = (lane & 3) << 1;    // 0,2,4,6
#pragma unroll
    for (int mi = 0; mi < 2; mi++)
#pragma unroll
        for (int ni = 0; ni < 8; ni++)
#pragma unroll
            for (int rh = 0; rh < 2; rh++) {
                int r  = rm + mi * 16 + tg + rh * 8;
                int c0 = cn + ni * 8 + tc;
                int gi = i0 + r;
                if (gi < cnt) {
                    float v0 = acc[mi][ni][2 * rh];
                    float v1 = acc[mi][ni][2 * rh + 1];
                    if (MODE == 0) {
                        float sw = row_w_s[r];
                        float f0 = sw * fmaxf(v0, 0.f); f0 *= f0;
                        float f1 = sw * fmaxf(v1, 0.f); f1 *= f1;
                        __half2 h2 = __floats2half2_rn(f0, f1);
                        *(__half2*)(g_h + ((size_t)e * T_TOK + gi) * HID + j0 + c0) = h2;
                    } else {
                        int tk = row_tok_s[r];
                        int t = tk & 0xFFF, slot = tk >> 12;
                        float2 v2 = make_float2(v0, v1);
                        *(float2*)(g_part + (size_t)slot * TD + (size_t)t * DIM + j0 + c0) = v2;
                    }
                }
            }
}

// ---------------- final combine ----------------------------------------------
__global__ void combine_kernel(float* __restrict__ out) {
    int i = (blockIdx.x * blockDim.x + threadIdx.x) * 4;
    if (i >= TD) return;
    float4 a = *(const float4*)(g_part + i);
    float4 b = *(const float4*)(g_part + TD + i);
    float4 r = make_float4(a.x + b.x, a.y + b.y, a.z + b.z, a.w + b.w);
    *(float4*)(out + i) = r;
}

// ---------------- launch -----------------------------------------------------
extern "C" void kernel_launch(void* const* d_in, const int* in_sizes, int n_in,
                              void* d_out, int out_size) {
    const float* x      = (const float*)d_in[0];
    const float* gate_w = (const float*)d_in[1];
    const float* w_up   = (const float*)d_in[2];
    const float* w_down = (const float*)d_in[3];
    const float* bias   = (const float*)d_in[4];
    float* out = (float*)d_out;

    constexpr int SMEM_UP   = 3 * 3 * PB;   // 92160
    constexpr int SMEM_DOWN = 4 * 2 * PB;   // 81920
    cudaFuncSetAttribute(moe_gemm_kernel<0>,
                         cudaFuncAttributeMaxDynamicSharedMemorySize, SMEM_UP);
    cudaFuncSetAttribute(moe_gemm_kernel<1>,
                         cudaFuncAttributeMaxDynamicSharedMemorySize, SMEM_DOWN);

    init_counts_kernel<<<1, 32>>>();
    router_kernel<<<T_TOK / 4, 128>>>(x, gate_w, bias);

    {
        constexpr int NTOT = T_TOK * DIM + NEXP * HID * DIM + NEXP * DIM * HID;
        prepass_kernel<<<(NTOT / 4 + 255) / 256, 256>>>(x, w_up, w_down);
    }

    moe_gemm_kernel<0><<<dim3(HID / BN, T_TOK / BM, NEXP), 256, SMEM_UP>>>();
    moe_gemm_kernel<1><<<dim3(DIM / BN, T_TOK / BM, NEXP), 256, SMEM_DOWN>>>();
    combine_kernel<<<TD / 4 / 256, 256>>>(out);
    (void)in_sizes; (void)n_in;
}

// round 12
// speedup vs baseline: 1.0637x; 1.0637x over previous
#include <cuda_runtime.h>
#include <cuda_bf16.h>
#include <cuda_fp16.h>
#include <math.h>
#include <stdint.h>

#define T_TOK 2048
#define DIM   1024
#define NEXP  8
#define HID   2048

#define BM 128
#define BN 128
#define BK 64              // K elements per chunk (128B payload per row)
#define ROWB 144           // padded row stride bytes (9 x 16B) -> conflict-free ldmatrix
#define PB (128 * ROWB)    // plane bytes = 18432

#define TD (T_TOK * DIM)

// ---------------- scratch (device globals; no allocation allowed) ----------
__device__ int   g_cnt[NEXP];
__device__ int   g_tok[NEXP * T_TOK];    // t | (slot << 12)
__device__ float g_wgt[NEXP * T_TOK];
__device__ __align__(256) __half g_x_hi[T_TOK * DIM];
__device__ __align__(256) __half g_x_lo[T_TOK * DIM];
__device__ __align__(256) __half g_wu[NEXP * HID * DIM];
__device__ __align__(256) __half g_wd[NEXP * DIM * HID];
__device__ __align__(256) __half g_h[(size_t)NEXP * T_TOK * HID];
__device__ __align__(256) float  g_part[2 * TD];   // down partials (slot 0 / 1)

// ---------------- helpers ---------------------------------------------------
__device__ __forceinline__ uint32_t smem_u32(const void* p) {
    return (uint32_t)__cvta_generic_to_shared(p);
}
__device__ __forceinline__ void cpa16(uint32_t dst, const void* src) {
    asm volatile("cp.async.cg.shared.global [%0], [%1], 16;\n"
                 :: "r"(dst), "l"(src) : "memory");
}
__device__ __forceinline__ void ldmx4(uint32_t& r0, uint32_t& r1, uint32_t& r2,
                                      uint32_t& r3, uint32_t addr) {
    asm volatile("ldmatrix.sync.aligned.m8n8.x4.shared.b16 {%0,%1,%2,%3}, [%4];\n"
                 : "=r"(r0), "=r"(r1), "=r"(r2), "=r"(r3) : "r"(addr));
}
__device__ __forceinline__ void mma_fp16(float* d, const uint32_t* a, const uint32_t* b) {
    asm volatile("mma.sync.aligned.m16n8k16.row.col.f32.f16.f16.f32 "
                 "{%0,%1,%2,%3}, {%4,%5,%6,%7}, {%8,%9}, {%0,%1,%2,%3};\n"
                 : "+f"(d[0]), "+f"(d[1]), "+f"(d[2]), "+f"(d[3])
                 : "r"(a[0]), "r"(a[1]), "r"(a[2]), "r"(a[3]), "r"(b[0]), "r"(b[1]));
}

// ---------------- router ----------------------------------------------------
__global__ void init_counts_kernel() {
    if (threadIdx.x < NEXP) g_cnt[threadIdx.x] = 0;
}

__global__ void router_kernel(const float* __restrict__ x,
                              const float* __restrict__ gate_w,
                              const float* __restrict__ bias) {
    int warp = threadIdx.x >> 5;
    int lane = threadIdx.x & 31;
    int t = blockIdx.x * 4 + warp;
    if (t >= T_TOK) return;

    float s[NEXP];
#pragma unroll
    for (int e = 0; e < NEXP; e++) s[e] = 0.f;
    const float* xr = x + (size_t)t * DIM;
    for (int d = lane; d < DIM; d += 32) {
        float xv = xr[d];
#pragma unroll
        for (int e = 0; e < NEXP; e++) s[e] += xv * gate_w[e * DIM + d];
    }
#pragma unroll
    for (int e = 0; e < NEXP; e++)
#pragma unroll
        for (int o = 16; o > 0; o >>= 1)
            s[e] += __shfl_xor_sync(0xffffffffu, s[e], o);

    if (lane == 0) {
        float sig[NEXP], b[NEXP];
#pragma unroll
        for (int e = 0; e < NEXP; e++) {
            sig[e] = 1.f / (1.f + expf(-s[e]));
            b[e] = sig[e] + bias[e];
        }
        int e0 = 0;
        for (int e = 1; e < NEXP; e++) if (b[e] > b[e0]) e0 = e;
        int e1 = -1;
        for (int e = 0; e < NEXP; e++) {
            if (e == e0) continue;
            if (e1 < 0 || b[e] > b[e1]) e1 = e;
        }
        int p0 = atomicAdd(&g_cnt[e0], 1);
        g_tok[e0 * T_TOK + p0] = t;                 // slot 0
        g_wgt[e0 * T_TOK + p0] = sig[e0];
        int p1 = atomicAdd(&g_cnt[e1], 1);
        g_tok[e1 * T_TOK + p1] = t | (1 << 12);     // slot 1
        g_wgt[e1 * T_TOK + p1] = sig[e1];
    }
}

// ---------------- fused prepass ----------------------------------------------
// region 0: x -> fp16 hi/lo split; region 1: w_up -> fp16; region 2: w_down -> fp16
__global__ void prepass_kernel(const float* __restrict__ x,
                               const float* __restrict__ w_up,
                               const float* __restrict__ w_down) {
    constexpr int NX  = T_TOK * DIM;
    constexpr int NWU = NEXP * HID * DIM;
    constexpr int NWD = NEXP * DIM * HID;
    int i4 = (blockIdx.x * blockDim.x + threadIdx.x) * 4;
    if (i4 < NX) {
        float4 v = *(const float4*)(x + i4);
        float f[4] = {v.x, v.y, v.z, v.w};
        __half h[4], l[4];
#pragma unroll
        for (int j = 0; j < 4; j++) {
            h[j] = __float2half_rn(f[j]);
            l[j] = __float2half_rn(f[j] - __half2float(h[j]));
        }
        *(uint2*)(g_x_hi + i4) = *(uint2*)h;
        *(uint2*)(g_x_lo + i4) = *(uint2*)l;
    } else if (i4 < NX + NWU + NWD) {
        const float* src; __half* dst; int off;
        if (i4 < NX + NWU) { off = i4 - NX;       src = w_up;   dst = g_wu; }
        else               { off = i4 - NX - NWU; src = w_down; dst = g_wd; }
        float4 v = *(const float4*)(src + off);
        __half2 a = __floats2half2_rn(v.x, v.y);
        __half2 b = __floats2half2_rn(v.z, v.w);
        *(uint2*)(dst + off) = make_uint2(*(uint32_t*)&a, *(uint32_t*)&b);
    }
}

// ---------------- grouped GEMM ----------------------------------------------
// MODE 0 (up):   2-term fp16: z = Ahi@B + Alo@B; A = gather(x hi/lo), B = wu
//                epilogue h = (s*relu(z))^2 -> fp16   [3 planes, 2 stages]
// MODE 1 (down): 1-term fp16: A = h, B = wd; epilogue STG to g_part[slot]
//                [2 planes, 3 stages]
template <int MODE>
__global__ __launch_bounds__(256, 2)
void moe_gemm_kernel() {
    constexpr int KT     = (MODE == 0) ? DIM : HID;
    constexpr int NC     = KT / BK;               // up: 16, down: 32
    constexpr int STAGES = (MODE == 0) ? 2 : 3;
    constexpr int PLANES = (MODE == 0) ? 3 : 2;   // up: Ahi,Alo,B; down: A,B

    const int e   = blockIdx.z;
    const int cnt = g_cnt[e];
    const int i0  = blockIdx.y * BM;
    if (i0 >= cnt) return;
    const int j0  = blockIdx.x * BN;

    extern __shared__ __align__(1024) char smem_dyn[];
    __shared__ int   row_tok_s[BM];
    __shared__ float row_w_s[BM];
    const uint32_t sbase = smem_u32(smem_dyn);

    const int tid = threadIdx.x, warp = tid >> 5, lane = tid & 31;
    const int wm = warp & 3, wn = warp >> 2;
    const int rm = wm * 32, cn = wn * 64;

    for (int i = tid; i < BM; i += 256) {
        int gi = i0 + i; int tk = 0; float w = 0.f;
        if (gi < cnt) { tk = g_tok[e * T_TOK + gi]; w = g_wgt[e * T_TOK + gi]; }
        row_tok_s[i] = tk; row_w_s[i] = w;
    }
    __syncthreads();

    float acc[2][8][4];
#pragma unroll
    for (int a = 0; a < 2; a++)
#pragma unroll
        for (int b = 0; b < 8; b++)
#pragma unroll
            for (int c = 0; c < 4; c++) acc[a][b][c] = 0.f;

    auto load_chunk = [&](int c) {
        const int k0 = c * BK;
        const uint32_t st = sbase + (uint32_t)(c % STAGES) * PLANES * PB;
#pragma unroll
        for (int p = 0; p < PLANES; p++) {
#pragma unroll
            for (int q = 0; q < 4; q++) {
                int id  = tid + q * 256;          // 0..1023
                int r   = id >> 3;                // row 0..127
                int c16 = id & 7;                 // 16B chunk in 128B row payload
                const void* src;
                if (MODE == 0) {
                    if (p < 2) {
                        const __half* base = (p == 0) ? g_x_hi : g_x_lo;
                        src = base + (size_t)(row_tok_s[r] & 0xFFF) * DIM + k0 + c16 * 8;
                    } else {
                        src = g_wu + ((size_t)e * HID + j0 + r) * DIM + k0 + c16 * 8;
                    }
                } else {
                    if (p == 0)
                        src = g_h + ((size_t)e * T_TOK + i0 + r) * HID + k0 + c16 * 8;
                    else
                        src = g_wd + ((size_t)e * DIM + j0 + r) * HID + k0 + c16 * 8;
                }
                cpa16(st + (uint32_t)p * PB + (uint32_t)(r * ROWB + c16 * 16), src);
            }
        }
        asm volatile("cp.async.commit_group;\n" ::: "memory");
    };

    // prologue: fill STAGES-1 stages
#pragma unroll
    for (int c = 0; c < STAGES - 1; c++) load_chunk(c);

    for (int c = 0; c < NC; c++) {
        // Steady state: wait_group(STAGES-2) retires exactly chunk c.
        // Tail (no further commits): must drain fully.
        if (c + STAGES - 1 < NC) {
            asm volatile("cp.async.wait_group %0;\n" :: "n"(STAGES - 2) : "memory");
        } else {
            asm volatile("cp.async.wait_group 0;\n" ::: "memory");
        }
        __syncthreads();   // chunk c visible; all warps done with chunk c-1
        if (c + STAGES - 1 < NC) load_chunk(c + STAGES - 1);

        const uint32_t st = sbase + (uint32_t)(c % STAGES) * PLANES * PB;
#pragma unroll
        for (int kk = 0; kk < BK; kk += 16) {
            if (MODE == 0) {
                uint32_t af[2][2][4];
#pragma unroll
                for (int part = 0; part < 2; part++)
#pragma unroll
                    for (int mi = 0; mi < 2; mi++) {
                        uint32_t addr = st + (uint32_t)part * PB +
                            (uint32_t)((rm + mi * 16 + (lane & 15)) * ROWB +
                                       (kk + (lane >> 4) * 8) * 2);
                        ldmx4(af[part][mi][0], af[part][mi][1],
                              af[part][mi][2], af[part][mi][3], addr);
                    }
                uint32_t bf[8][2];
#pragma unroll
                for (int nb = 0; nb < 4; nb++) {
                    int nrow = cn + nb * 16 + (lane & 7) + (((lane >> 4) & 1) << 3);
                    int kcol = kk + ((lane & 8) ? 8 : 0);
                    uint32_t addr = st + 2u * PB + (uint32_t)(nrow * ROWB + kcol * 2);
                    uint32_t r0, r1, r2, r3;
                    ldmx4(r0, r1, r2, r3, addr);
                    bf[nb * 2][0] = r0;      bf[nb * 2][1] = r1;
                    bf[nb * 2 + 1][0] = r2;  bf[nb * 2 + 1][1] = r3;
                }
#pragma unroll
                for (int mi = 0; mi < 2; mi++)
#pragma unroll
                    for (int ni = 0; ni < 8; ni++) {
                        mma_fp16(acc[mi][ni], af[0][mi], bf[ni]);
                        mma_fp16(acc[mi][ni], af[1][mi], bf[ni]);
                    }
            } else {
                uint32_t af[2][4];
#pragma unroll
                for (int mi = 0; mi < 2; mi++) {
                    uint32_t addr = st +
                        (uint32_t)((rm + mi * 16 + (lane & 15)) * ROWB +
                                   (kk + (lane >> 4) * 8) * 2);
                    ldmx4(af[mi][0], af[mi][1], af[mi][2], af[mi][3], addr);
                }
                uint32_t bf[8][2];
#pragma unroll
                for (int nb = 0; nb < 4; nb++) {
                    int nrow = cn + nb * 16 + (lane & 7) + (((lane >> 4) & 1) << 3);
                    int kcol = kk + ((lane & 8) ? 8 : 0);
                    uint32_t addr = st + PB + (uint32_t)(nrow * ROWB + kcol * 2);
                    uint32_t r0, r1, r2, r3;
                    ldmx4(r0, r1, r2, r3, addr);
                    bf[nb * 2][0] = r0;      bf[nb * 2][1] = r1;
                    bf[nb * 2 + 1][0] = r2;  bf[nb * 2 + 1][1] = r3;
                }
#pragma unroll
                for (int mi = 0; mi < 2; mi++)
#pragma unroll
                    for (int ni = 0; ni < 8; ni++)
                        mma_fp16(acc[mi][ni], af[mi], bf[ni]);
            }
        }
    }

    // ---------------- epilogue ----------------
    const int tg = lane >> 2;          // 0..7
    const int tc = (lane & 3) << 1;    // 0,2,4,6
#pragma unroll
    for (int mi = 0; mi < 2; mi++)
#pragma unroll
        for (int ni = 0; ni < 8; ni++)
#pragma unroll
            for (int rh = 0; rh < 2; rh++) {
                int r  = rm + mi * 16 + tg + rh * 8;
                int c0 = cn + ni * 8 + tc;
                int gi = i0 + r;
                if (gi < cnt) {
                    float v0 = acc[mi][ni][2 * rh];
                    float v1 = acc[mi][ni][2 * rh + 1];
                    if (MODE == 0) {
                        float sw = row_w_s[r];
                        float f0 = sw * fmaxf(v0, 0.f); f0 *= f0;
                        float f1 = sw * fmaxf(v1, 0.f); f1 *= f1;
                        __half2 h2 = __floats2half2_rn(f0, f1);
                        *(__half2*)(g_h + ((size_t)e * T_TOK + gi) * HID + j0 + c0) = h2;
                    } else {
                        int tk = row_tok_s[r];
                        int t = tk & 0xFFF, slot = tk >> 12;
                        float2 v2 = make_float2(v0, v1);
                        *(float2*)(g_part + (size_t)slot * TD + (size_t)t * DIM + j0 + c0) = v2;
                    }
                }
            }
}

// ---------------- final combine ----------------------------------------------
__global__ void combine_kernel(float* __restrict__ out) {
    int i = (blockIdx.x * blockDim.x + threadIdx.x) * 4;
    if (i >= TD) return;
    float4 a = *(const float4*)(g_part + i);
    float4 b = *(const float4*)(g_part + TD + i);
    float4 r = make_float4(a.x + b.x, a.y + b.y, a.z + b.z, a.w + b.w);
    *(float4*)(out + i) = r;
}

// ---------------- launch -----------------------------------------------------
extern "C" void kernel_launch(void* const* d_in, const int* in_sizes, int n_in,
                              void* d_out, int out_size) {
    const float* x      = (const float*)d_in[0];
    const float* gate_w = (const float*)d_in[1];
    const float* w_up   = (const float*)d_in[2];
    const float* w_down = (const float*)d_in[3];
    const float* bias   = (const float*)d_in[4];
    float* out = (float*)d_out;

    constexpr int SMEM_UP   = 2 * 3 * PB;   // 110592
    constexpr int SMEM_DOWN = 3 * 2 * PB;   // 110592
    cudaFuncSetAttribute(moe_gemm_kernel<0>,
                         cudaFuncAttributeMaxDynamicSharedMemorySize, SMEM_UP);
    cudaFuncSetAttribute(moe_gemm_kernel<1>,
                         cudaFuncAttributeMaxDynamicSharedMemorySize, SMEM_DOWN);

    init_counts_kernel<<<1, 32>>>();
    router_kernel<<<T_TOK / 4, 128>>>(x, gate_w, bias);

    {
        constexpr int NTOT = T_TOK * DIM + NEXP * HID * DIM + NEXP * DIM * HID;
        prepass_kernel<<<(NTOT / 4 + 255) / 256, 256>>>(x, w_up, w_down);
    }

    moe_gemm_kernel<0><<<dim3(HID / BN, T_TOK / BM, NEXP), 256, SMEM_UP>>>();
    moe_gemm_kernel<1><<<dim3(DIM / BN, T_TOK / BM, NEXP), 256, SMEM_DOWN>>>();
    combine_kernel<<<TD / 4 / 256, 256>>>(out);
    (void)in_sizes; (void)n_in;
}